// round 15
// baseline (speedup 1.0000x reference)
#include <cuda_runtime.h>

// Problem constants (fixed by the dataset): B=2, C=6, H=W=512, radii {2,4}
#define HH 512
#define WW 512
#define HW (HH * WW)
#define CC 6
#define CCA_EPS 1e-6f

#define TB 128  // threads per block = output columns per block
#define TR 16   // output rows per block

typedef unsigned long long u64;

// ---------- packed f32x2 helpers (sm_103a FFMA2 path) ----------
static __device__ __forceinline__ u64 pk2(float lo, float hi) {
    u64 r; asm("mov.b64 %0, {%1, %2};" : "=l"(r) : "f"(lo), "f"(hi)); return r;
}
static __device__ __forceinline__ u64 bc2(float v) {
    u64 r; asm("mov.b64 %0, {%1, %1};" : "=l"(r) : "f"(v)); return r;
}
static __device__ __forceinline__ void fma2(u64& d, u64 a, u64 b) {
    asm("fma.rn.f32x2 %0, %1, %2, %0;" : "+l"(d) : "l"(a), "l"(b));
}
static __device__ __forceinline__ u64 fma2v(u64 d, u64 a, u64 b) {
    asm("fma.rn.f32x2 %0, %1, %2, %0;" : "+l"(d) : "l"(a), "l"(b));
    return d;
}
static __device__ __forceinline__ u64 mul2v(u64 a, u64 b) {
    u64 r; asm("mul.rn.f32x2 %0, %1, %2;" : "=l"(r) : "l"(a), "l"(b));
    return r;
}
static __device__ __forceinline__ void add2(u64& d, u64 a) {
    asm("add.rn.f32x2 %0, %0, %1;" : "+l"(d) : "l"(a));
}
static __device__ __forceinline__ void sub2(u64& d, u64 a) {
    asm("sub.rn.f32x2 %0, %0, %1;" : "+l"(d) : "l"(a));
}
static __device__ __forceinline__ void up2(u64 v, float& a, float& b) {
    asm("mov.b64 {%0, %1}, %2;" : "=f"(a), "=f"(b) : "l"(v));
}

static __device__ __forceinline__ int refl(int p, int n) {
    // jnp.pad mode='reflect': -1 -> 1, n -> n-2
    return p < 0 ? -p : (p >= n ? 2 * n - 2 - p : p);
}

// Packed lower-triangular index (i >= j)
static __device__ __host__ __forceinline__ constexpr int P(int i, int j) {
    return i * (i + 1) / 2 + j;
}

// Window-sum state, f32x2-packed along j.
struct Acc {
    u64 xx[9];   // XX triangle pairs: (1:01)(2:01)(3:01)(3:23)(4:01)(4:23)(5:01)(5:23)(5:45)
    u64 yy[9];
    u64 xy[18];  // full 6x6, row i pairs p=0..2
    u64 mx[3], my[3];
    float dxx[3];  // XX diag leftovers: (0,0) (2,2) (4,4)
    float dyy[3];
};

static __device__ __forceinline__ void acc_zero(Acc& A) {
#pragma unroll
    for (int t = 0; t < 9; t++) { A.xx[t] = 0ULL; A.yy[t] = 0ULL; }
#pragma unroll
    for (int t = 0; t < 18; t++) A.xy[t] = 0ULL;
#pragma unroll
    for (int t = 0; t < 3; t++) {
        A.mx[t] = 0ULL; A.my[t] = 0ULL; A.dxx[t] = 0.f; A.dyy[t] = 0.f;
    }
}

// One sample's FMA work: SGN=+1 add, SGN=-1 retire.
template <int SGN>
static __device__ __forceinline__ void sample_fma(const float xv[CC], const float yv[CC], Acc& A) {
    float mxv[CC], myv[CC];
#pragma unroll
    for (int a = 0; a < CC; a++) {
        mxv[a] = (SGN > 0) ? xv[a] : -xv[a];
        myv[a] = (SGN > 0) ? yv[a] : -yv[a];
    }
    u64 xp[3], yp[3];
#pragma unroll
    for (int p = 0; p < 3; p++) {
        xp[p] = pk2(xv[2 * p], xv[2 * p + 1]);
        yp[p] = pk2(yv[2 * p], yv[2 * p + 1]);
    }
    u64 bx[6], by[6];
#pragma unroll
    for (int a = 0; a < 6; a++) bx[a] = bc2(mxv[a]);
#pragma unroll
    for (int a = 1; a < 6; a++) by[a] = bc2(myv[a]);

    // XX triangle
    fma2(A.xx[0], bx[1], xp[0]);
    fma2(A.xx[1], bx[2], xp[0]);
    fma2(A.xx[2], bx[3], xp[0]); fma2(A.xx[3], bx[3], xp[1]);
    fma2(A.xx[4], bx[4], xp[0]); fma2(A.xx[5], bx[4], xp[1]);
    fma2(A.xx[6], bx[5], xp[0]); fma2(A.xx[7], bx[5], xp[1]); fma2(A.xx[8], bx[5], xp[2]);
    A.dxx[0] = fmaf(mxv[0], xv[0], A.dxx[0]);
    A.dxx[1] = fmaf(mxv[2], xv[2], A.dxx[1]);
    A.dxx[2] = fmaf(mxv[4], xv[4], A.dxx[2]);
    // YY triangle
    fma2(A.yy[0], by[1], yp[0]);
    fma2(A.yy[1], by[2], yp[0]);
    fma2(A.yy[2], by[3], yp[0]); fma2(A.yy[3], by[3], yp[1]);
    fma2(A.yy[4], by[4], yp[0]); fma2(A.yy[5], by[4], yp[1]);
    fma2(A.yy[6], by[5], yp[0]); fma2(A.yy[7], by[5], yp[1]); fma2(A.yy[8], by[5], yp[2]);
    A.dyy[0] = fmaf(myv[0], yv[0], A.dyy[0]);
    A.dyy[1] = fmaf(myv[2], yv[2], A.dyy[1]);
    A.dyy[2] = fmaf(myv[4], yv[4], A.dyy[2]);
    // XY full
#pragma unroll
    for (int i = 0; i < 6; i++) {
        fma2(A.xy[i * 3 + 0], bx[i], yp[0]);
        fma2(A.xy[i * 3 + 1], bx[i], yp[1]);
        fma2(A.xy[i * 3 + 2], bx[i], yp[2]);
    }
    // means
    if (SGN > 0) {
#pragma unroll
        for (int p = 0; p < 3; p++) { add2(A.mx[p], xp[p]); add2(A.my[p], yp[p]); }
    } else {
#pragma unroll
        for (int p = 0; p < 3; p++) { sub2(A.mx[p], xp[p]); sub2(A.my[p], yp[p]); }
    }
}

// ---------- shared-memory row staging ----------
// Slab layout: [col][ch] with ch in 0..11 (0-5 = x channels, 6-11 = y channels),
// 48 bytes per column -> LDS.128-friendly, conflict-free within quarter-warps.
#define SLABF (136 * 12)  // floats per slab (max SC=136)

// Stage one (reflected) image row into a slab. grow is pre-reflected.
template <int R>
static __device__ __forceinline__ void stage_row(float* __restrict__ slab,
                                                 const float* __restrict__ xb,
                                                 const float* __restrict__ yb,
                                                 int grow, int x0) {
    constexpr int SC = TB + 2 * R;
    constexpr int total = 12 * SC;
    const int rbase = grow * WW;
#pragma unroll
    for (int l = threadIdx.x; l < total; l += TB) {
        const int col = l % SC;
        const int ch = l / SC;
        const int g = refl(x0 - R + col, WW);
        const float* src = (ch < 6) ? (xb + ch * HW) : (yb + (ch - 6) * HW);
        slab[col * 12 + ch] = __ldg(src + rbase + g);
    }
}

template <int R>
static __device__ __forceinline__ void load12(const float* __restrict__ slab, int col,
                                              float xv[CC], float yv[CC]) {
    const float4* p = reinterpret_cast<const float4*>(slab + col * 12);
    const float4 a = p[0];
    const float4 b = p[1];
    const float4 c = p[2];
    xv[0] = a.x; xv[1] = a.y; xv[2] = a.z; xv[3] = a.w;
    xv[4] = b.x; xv[5] = b.y; yv[0] = b.z; yv[1] = b.w;
    yv[2] = c.x; yv[3] = c.y; yv[4] = c.z; yv[5] = c.w;
}

// In-place: packed-lower SPD matrix -> packed-lower inv(chol(c)).
static __device__ __forceinline__ void chol_inv6(float* c) {
    float L[21];  // off-diagonals hold L[i][j]; diagonal slots hold 1/L[j][j]
#pragma unroll
    for (int j = 0; j < 6; j++) {
        float d = c[P(j, j)];
#pragma unroll
        for (int k = 0; k < j; k++) d = fmaf(-L[P(j, k)], L[P(j, k)], d);
        const float rs = rsqrtf(d);
        L[P(j, j)] = rs;
#pragma unroll
        for (int i = j + 1; i < 6; i++) {
            float s = c[P(i, j)];
#pragma unroll
            for (int k = 0; k < j; k++) s = fmaf(-L[P(i, k)], L[P(j, k)], s);
            L[P(i, j)] = s * rs;
        }
    }
    // Forward substitution: M = L^{-1}, written back into c
#pragma unroll
    for (int j = 0; j < 6; j++) {
        c[P(j, j)] = L[P(j, j)];
#pragma unroll
        for (int i = j + 1; i < 6; i++) {
            float s = 0.f;
#pragma unroll
            for (int k = j; k < i; k++) s = fmaf(L[P(i, k)], c[P(k, j)], s);
            c[P(i, j)] = -L[P(i, i)] * s;
        }
    }
}

// Epilogue on RAW window sums (CCA is invariant to scaling cov by n).
template <int R>
static __device__ __forceinline__ float cca_epilogue(const Acc& A) {
    constexpr float inv_n = 1.0f / float((2 * R + 1) * (2 * R + 1));
    constexpr float neps = CCA_EPS * float((2 * R + 1) * (2 * R + 1));

    float sxm[6], sym[6];
#pragma unroll
    for (int p = 0; p < 3; p++) {
        up2(A.mx[p], sxm[2 * p], sxm[2 * p + 1]);
        up2(A.my[p], sym[2 * p], sym[2 * p + 1]);
    }
    const u64 cni = bc2(-inv_n);
    u64 nsmx[3], nsmy[3];  // -(S1)/n, packed pairs
#pragma unroll
    for (int p = 0; p < 3; p++) {
        nsmx[p] = mul2v(A.mx[p], cni);
        nsmy[p] = mul2v(A.my[p], cni);
    }
    u64 bx[6], by[6];
#pragma unroll
    for (int a = 0; a < 6; a++) { bx[a] = bc2(sxm[a]); by[a] = bc2(sym[a]); }

    // chat pairs = S2_pair + bc2(S1_i) * nsm_pair
    float cxx[21], cyy[21], cxy[36];
    {
        u64 t;
        t = fma2v(A.xx[0], bx[1], nsmx[0]); up2(t, cxx[P(1, 0)], cxx[P(1, 1)]);
        t = fma2v(A.xx[1], bx[2], nsmx[0]); up2(t, cxx[P(2, 0)], cxx[P(2, 1)]);
        t = fma2v(A.xx[2], bx[3], nsmx[0]); up2(t, cxx[P(3, 0)], cxx[P(3, 1)]);
        t = fma2v(A.xx[3], bx[3], nsmx[1]); up2(t, cxx[P(3, 2)], cxx[P(3, 3)]);
        t = fma2v(A.xx[4], bx[4], nsmx[0]); up2(t, cxx[P(4, 0)], cxx[P(4, 1)]);
        t = fma2v(A.xx[5], bx[4], nsmx[1]); up2(t, cxx[P(4, 2)], cxx[P(4, 3)]);
        t = fma2v(A.xx[6], bx[5], nsmx[0]); up2(t, cxx[P(5, 0)], cxx[P(5, 1)]);
        t = fma2v(A.xx[7], bx[5], nsmx[1]); up2(t, cxx[P(5, 2)], cxx[P(5, 3)]);
        t = fma2v(A.xx[8], bx[5], nsmx[2]); up2(t, cxx[P(5, 4)], cxx[P(5, 5)]);
        t = fma2v(A.yy[0], by[1], nsmy[0]); up2(t, cyy[P(1, 0)], cyy[P(1, 1)]);
        t = fma2v(A.yy[1], by[2], nsmy[0]); up2(t, cyy[P(2, 0)], cyy[P(2, 1)]);
        t = fma2v(A.yy[2], by[3], nsmy[0]); up2(t, cyy[P(3, 0)], cyy[P(3, 1)]);
        t = fma2v(A.yy[3], by[3], nsmy[1]); up2(t, cyy[P(3, 2)], cyy[P(3, 3)]);
        t = fma2v(A.yy[4], by[4], nsmy[0]); up2(t, cyy[P(4, 0)], cyy[P(4, 1)]);
        t = fma2v(A.yy[5], by[4], nsmy[1]); up2(t, cyy[P(4, 2)], cyy[P(4, 3)]);
        t = fma2v(A.yy[6], by[5], nsmy[0]); up2(t, cyy[P(5, 0)], cyy[P(5, 1)]);
        t = fma2v(A.yy[7], by[5], nsmy[1]); up2(t, cyy[P(5, 2)], cyy[P(5, 3)]);
        t = fma2v(A.yy[8], by[5], nsmy[2]); up2(t, cyy[P(5, 4)], cyy[P(5, 5)]);
#pragma unroll
        for (int i = 0; i < 6; i++) {
#pragma unroll
            for (int p = 0; p < 3; p++) {
                t = fma2v(A.xy[i * 3 + p], bx[i], nsmy[p]);
                up2(t, cxy[i * 6 + 2 * p], cxy[i * 6 + 2 * p + 1]);
            }
        }
    }
    // diagonal leftovers + n*eps
    float nsx0, nsx1, nsx2, nsx3, nsx4, nsx5, nsy0, nsy1, nsy2, nsy3, nsy4, nsy5;
    up2(nsmx[0], nsx0, nsx1); up2(nsmx[1], nsx2, nsx3); up2(nsmx[2], nsx4, nsx5);
    up2(nsmy[0], nsy0, nsy1); up2(nsmy[1], nsy2, nsy3); up2(nsmy[2], nsy4, nsy5);
    cxx[P(0, 0)] = fmaf(sxm[0], nsx0, A.dxx[0]) + neps;
    cxx[P(2, 2)] = fmaf(sxm[2], nsx2, A.dxx[1]) + neps;
    cxx[P(4, 4)] = fmaf(sxm[4], nsx4, A.dxx[2]) + neps;
    cxx[P(1, 1)] += neps; cxx[P(3, 3)] += neps; cxx[P(5, 5)] += neps;
    cyy[P(0, 0)] = fmaf(sym[0], nsy0, A.dyy[0]) + neps;
    cyy[P(2, 2)] = fmaf(sym[2], nsy2, A.dyy[1]) + neps;
    cyy[P(4, 4)] = fmaf(sym[4], nsy4, A.dyy[2]) + neps;
    cyy[P(1, 1)] += neps; cyy[P(3, 3)] += neps; cyy[P(5, 5)] += neps;

    chol_inv6(cxx);  // Mx = inv(chol(n*Cxx)), packed lower
    chol_inv6(cyy);  // My = inv(chol(n*Cyy)), packed lower

    // corr_ii = sum_{j<=i} sum_{k>=i} Mx[i,j] * (n*Cxy)[j,k] * My[k,i]
    float sim = 0.f;
#pragma unroll
    for (int i = 0; i < 6; i++) {
        float corr = 0.f;
#pragma unroll
        for (int k = i; k < 6; k++) {
            float t = 0.f;
#pragma unroll
            for (int j = 0; j <= i; j++) t = fmaf(cxx[P(i, j)], cxy[j * 6 + k], t);
            corr = fmaf(t, cyy[P(k, i)], corr);
        }
        sim += fabsf(corr);
    }
    return sim * (1.0f / 6.0f);
}

// ---------- tile driver ----------
// Block = 128 threads = 128 adjacent output columns, sliding down TR rows.
// Double-buffered smem staging: slabs 0/1 alternate during prime (1 row each),
// slab pairs {0,1} / {2,3} alternate during the main loop (add+retire rows).
template <int R>
static __device__ void run_tile(const float* __restrict__ xb,
                                const float* __restrict__ yb,
                                float* __restrict__ ob,
                                int x0, int y0, int ridx, float* __restrict__ sbuf) {
    const int tid = threadIdx.x;
    Acc A;
    acc_zero(A);

    // ---- prime: rows y0-R-1 .. y0+R-1 (2R+1 rows; y0-R-1 is the stale row
    // retired by the first fused main step) ----
    stage_row<R>(sbuf /*slab0*/, xb, yb, refl(y0 - R - 1, HH), x0);
#pragma unroll 1
    for (int g = 0; g < 2 * R; ++g) {
        __syncthreads();
        stage_row<R>(sbuf + ((g + 1) & 1) * SLABF, xb, yb, refl(y0 - R + g, HH), x0);
        const float* cur = sbuf + (g & 1) * SLABF;
#pragma unroll 1
        for (int dx = 0; dx <= 2 * R; ++dx) {
            float xv[CC], yv[CC];
            load12<R>(cur, tid + dx, xv, yv);
            sample_fma<1>(xv, yv, A);
        }
    }
    // last prime row (g = 2R) is in slab[0]; overlap its accumulation with
    // staging the first main row-pair into slabs {2,3}.
    __syncthreads();
    stage_row<R>(sbuf + 2 * SLABF, xb, yb, refl(y0 + R, HH), x0);
    stage_row<R>(sbuf + 3 * SLABF, xb, yb, refl(y0 - R - 1, HH), x0);
    {
        const float* cur = sbuf + ((2 * R) & 1) * SLABF;
#pragma unroll 1
        for (int dx = 0; dx <= 2 * R; ++dx) {
            float xv[CC], yv[CC];
            load12<R>(cur, tid + dx, xv, yv);
            sample_fma<1>(xv, yv, A);
        }
    }

    // ---- main loop ----
    int p = 1;  // current pair: 1 -> slabs {2,3}, 0 -> slabs {0,1}
#pragma unroll 1
    for (int yy = y0; yy < y0 + TR; ++yy) {
        __syncthreads();
        if (yy + 1 < y0 + TR) {
            float* nx = sbuf + 2 * (1 - p) * SLABF;
            stage_row<R>(nx, xb, yb, refl(yy + 1 + R, HH), x0);
            stage_row<R>(nx + SLABF, xb, yb, refl(yy - R, HH), x0);
        }
        const float* curA = sbuf + 2 * p * SLABF;        // add row (yy+R)
        const float* curR = curA + SLABF;                // retire row (yy-R-1)
#pragma unroll (R == 2 ? 5 : 3)
        for (int dx = 0; dx <= 2 * R; ++dx) {
            float xa[CC], ya[CC], xr[CC], yr[CC];
            load12<R>(curA, tid + dx, xa, ya);
            load12<R>(curR, tid + dx, xr, yr);
            sample_fma<1>(xa, ya, A);
            sample_fma<-1>(xr, yr, A);
        }
        const float sim = cca_epilogue<R>(A);
        ob[((yy * WW + x0 + tid) << 1) + ridx] = sim;
        p ^= 1;
    }
}

__global__ void __launch_bounds__(TB, 3)
PatchCCAConv_kernel(const float* __restrict__ x, const float* __restrict__ y,
                    float* __restrict__ out) {
    __shared__ __align__(16) float sbuf[4 * SLABF];  // 4 slabs, ~26 KB
    // z = 0,1 -> r=4 (long blocks scheduled first); z = 2,3 -> r=2
    const int b = blockIdx.z & 1;
    const bool is_r4 = blockIdx.z < 2;
    const int x0 = blockIdx.x * TB;
    const int y0 = blockIdx.y * TR;
    const float* xb = x + b * CC * HW;
    const float* yb = y + b * CC * HW;
    float* ob = out + b * (HH * WW * 2);
    if (is_r4)
        run_tile<4>(xb, yb, ob, x0, y0, 1, sbuf);
    else
        run_tile<2>(xb, yb, ob, x0, y0, 0, sbuf);
}

extern "C" void kernel_launch(void* const* d_in, const int* in_sizes, int n_in,
                              void* d_out, int out_size) {
    const float* x = (const float*)d_in[0];
    const float* y = (const float*)d_in[1];
    float* out = (float*)d_out;
    (void)in_sizes; (void)n_in; (void)out_size;

    dim3 block(TB, 1, 1);
    dim3 grid(WW / TB, HH / TR, 4);  // (4, 32, 4): z<2 r=4, z>=2 r=2
    PatchCCAConv_kernel<<<grid, block>>>(x, y, out);
}

// round 17
// speedup vs baseline: 2.6641x; 2.6641x over previous
#include <cuda_runtime.h>

// Problem constants (fixed by the dataset): B=2, C=6, H=W=512, radii {2,4}
#define HH 512
#define WW 512
#define HW (HH * WW)
#define CC 6
#define CCA_EPS 1e-6f

#define TB 128   // threads per block = output columns per block
#define TR 16    // output rows per block
#define SLABC 136               // cols per row-slab (global cols x0-4 .. x0+131)
#define SLABF (12 * SLABC)      // floats per row-slab (12 channels)
#define NPAIR 3                 // ring of 3 pair-slots (6 slabs)

typedef unsigned long long u64;

// ---------- packed f32x2 helpers (sm_103a FFMA2 path) ----------
static __device__ __forceinline__ u64 pk2(float lo, float hi) {
    u64 r; asm("mov.b64 %0, {%1, %2};" : "=l"(r) : "f"(lo), "f"(hi)); return r;
}
static __device__ __forceinline__ u64 bc2(float v) {
    u64 r; asm("mov.b64 %0, {%1, %1};" : "=l"(r) : "f"(v)); return r;
}
static __device__ __forceinline__ void fma2(u64& d, u64 a, u64 b) {
    asm("fma.rn.f32x2 %0, %1, %2, %0;" : "+l"(d) : "l"(a), "l"(b));
}
static __device__ __forceinline__ u64 fma2v(u64 d, u64 a, u64 b) {
    asm("fma.rn.f32x2 %0, %1, %2, %0;" : "+l"(d) : "l"(a), "l"(b));
    return d;
}
static __device__ __forceinline__ u64 mul2v(u64 a, u64 b) {
    u64 r; asm("mul.rn.f32x2 %0, %1, %2;" : "=l"(r) : "l"(a), "l"(b));
    return r;
}
static __device__ __forceinline__ void add2(u64& d, u64 a) {
    asm("add.rn.f32x2 %0, %0, %1;" : "+l"(d) : "l"(a));
}
static __device__ __forceinline__ void sub2(u64& d, u64 a) {
    asm("sub.rn.f32x2 %0, %0, %1;" : "+l"(d) : "l"(a));
}
static __device__ __forceinline__ void up2(u64 v, float& a, float& b) {
    asm("mov.b64 {%0, %1}, %2;" : "=f"(a), "=f"(b) : "l"(v));
}

// ---------- cp.async helpers ----------
static __device__ __forceinline__ void cp16(void* smem_dst, const float* gsrc) {
    unsigned d = (unsigned)__cvta_generic_to_shared(smem_dst);
    asm volatile("cp.async.cg.shared.global [%0], [%1], 16;" :: "r"(d), "l"(gsrc) : "memory");
}
static __device__ __forceinline__ void cp_commit() {
    asm volatile("cp.async.commit_group;" ::: "memory");
}
static __device__ __forceinline__ void cp_wait2() {
    asm volatile("cp.async.wait_group 2;" ::: "memory");
}

static __device__ __forceinline__ int refl(int p, int n) {
    // jnp.pad mode='reflect': -1 -> 1, n -> n-2
    return p < 0 ? -p : (p >= n ? 2 * n - 2 - p : p);
}

// Packed lower-triangular index (i >= j)
static __device__ __host__ __forceinline__ constexpr int P(int i, int j) {
    return i * (i + 1) / 2 + j;
}

// Window-sum state, f32x2-packed along j.
struct Acc {
    u64 xx[9];   // XX triangle pairs: (1:01)(2:01)(3:01)(3:23)(4:01)(4:23)(5:01)(5:23)(5:45)
    u64 yy[9];
    u64 xy[18];  // full 6x6, row i pairs p=0..2
    u64 mx[3], my[3];
    float dxx[3];  // XX diag leftovers: (0,0) (2,2) (4,4)
    float dyy[3];
};

static __device__ __forceinline__ void acc_zero(Acc& A) {
#pragma unroll
    for (int t = 0; t < 9; t++) { A.xx[t] = 0ULL; A.yy[t] = 0ULL; }
#pragma unroll
    for (int t = 0; t < 18; t++) A.xy[t] = 0ULL;
#pragma unroll
    for (int t = 0; t < 3; t++) {
        A.mx[t] = 0ULL; A.my[t] = 0ULL; A.dxx[t] = 0.f; A.dyy[t] = 0.f;
    }
}

// One sample's FMA work: SGN=+1 add, SGN=-1 retire.
template <int SGN>
static __device__ __forceinline__ void sample_fma(const float xv[CC], const float yv[CC], Acc& A) {
    float mxv[CC], myv[CC];
#pragma unroll
    for (int a = 0; a < CC; a++) {
        mxv[a] = (SGN > 0) ? xv[a] : -xv[a];
        myv[a] = (SGN > 0) ? yv[a] : -yv[a];
    }
    u64 xp[3], yp[3];
#pragma unroll
    for (int p = 0; p < 3; p++) {
        xp[p] = pk2(xv[2 * p], xv[2 * p + 1]);
        yp[p] = pk2(yv[2 * p], yv[2 * p + 1]);
    }
    u64 bx[6], by[6];
#pragma unroll
    for (int a = 0; a < 6; a++) bx[a] = bc2(mxv[a]);
#pragma unroll
    for (int a = 1; a < 6; a++) by[a] = bc2(myv[a]);

    // XX triangle
    fma2(A.xx[0], bx[1], xp[0]);
    fma2(A.xx[1], bx[2], xp[0]);
    fma2(A.xx[2], bx[3], xp[0]); fma2(A.xx[3], bx[3], xp[1]);
    fma2(A.xx[4], bx[4], xp[0]); fma2(A.xx[5], bx[4], xp[1]);
    fma2(A.xx[6], bx[5], xp[0]); fma2(A.xx[7], bx[5], xp[1]); fma2(A.xx[8], bx[5], xp[2]);
    A.dxx[0] = fmaf(mxv[0], xv[0], A.dxx[0]);
    A.dxx[1] = fmaf(mxv[2], xv[2], A.dxx[1]);
    A.dxx[2] = fmaf(mxv[4], xv[4], A.dxx[2]);
    // YY triangle
    fma2(A.yy[0], by[1], yp[0]);
    fma2(A.yy[1], by[2], yp[0]);
    fma2(A.yy[2], by[3], yp[0]); fma2(A.yy[3], by[3], yp[1]);
    fma2(A.yy[4], by[4], yp[0]); fma2(A.yy[5], by[4], yp[1]);
    fma2(A.yy[6], by[5], yp[0]); fma2(A.yy[7], by[5], yp[1]); fma2(A.yy[8], by[5], yp[2]);
    A.dyy[0] = fmaf(myv[0], yv[0], A.dyy[0]);
    A.dyy[1] = fmaf(myv[2], yv[2], A.dyy[1]);
    A.dyy[2] = fmaf(myv[4], yv[4], A.dyy[2]);
    // XY full
#pragma unroll
    for (int i = 0; i < 6; i++) {
        fma2(A.xy[i * 3 + 0], bx[i], yp[0]);
        fma2(A.xy[i * 3 + 1], bx[i], yp[1]);
        fma2(A.xy[i * 3 + 2], bx[i], yp[2]);
    }
    // means
    if (SGN > 0) {
#pragma unroll
        for (int p = 0; p < 3; p++) { add2(A.mx[p], xp[p]); add2(A.my[p], yp[p]); }
    } else {
#pragma unroll
        for (int p = 0; p < 3; p++) { sub2(A.mx[p], xp[p]); sub2(A.my[p], yp[p]); }
    }
}

// ---------- async row staging ----------
// Slab layout [ch][col]: 12 channels (0-5 x, 6-11 y) x 136 cols.
// Slab col c <-> global col x0-4+c. 34 aligned 16B chunks per channel row.
static __device__ __forceinline__ void stage_row_async(float* __restrict__ slab,
                                                       const float* __restrict__ xb,
                                                       const float* __restrict__ yb,
                                                       int grow, int x0) {
    const int g0 = x0 - 4;
    const int rbase = grow * WW;
#pragma unroll 1
    for (int t = threadIdx.x; t < 12 * 34; t += TB) {
        const int ch = t / 34;
        const int k = t - ch * 34;
        const int gc = g0 + 4 * k;
        const float* plane = (ch < 6) ? (xb + ch * HW) : (yb + (ch - 6) * HW);
        if ((unsigned)gc <= (unsigned)(WW - 4)) {
            cp16(slab + ch * SLABC + 4 * k, plane + rbase + gc);
        }
    }
    // Edge fixups (reflected columns), only for the two edge block-columns.
    if (x0 == 0) {
#pragma unroll 1
        for (int t = threadIdx.x; t < 48; t += TB) {
            const int ch = t >> 2, c = t & 3;  // slab cols 0..3 <-> global -4+c -> refl 4-c
            const float* plane = (ch < 6) ? (xb + ch * HW) : (yb + (ch - 6) * HW);
            slab[ch * SLABC + c] = __ldg(plane + rbase + (4 - c));
        }
    } else if (x0 == WW - TB) {
#pragma unroll 1
        for (int t = threadIdx.x; t < 48; t += TB) {
            const int ch = t >> 2, c = t & 3;  // slab cols 132..135 <-> global 512+c -> refl 510-c
            const float* plane = (ch < 6) ? (xb + ch * HW) : (yb + (ch - 6) * HW);
            slab[ch * SLABC + 132 + c] = __ldg(plane + rbase + (510 - c));
        }
    }
}

static __device__ __forceinline__ void load12s(const float* __restrict__ slab, int col,
                                               float xv[CC], float yv[CC]) {
#pragma unroll
    for (int a = 0; a < 6; a++) xv[a] = slab[a * SLABC + col];
#pragma unroll
    for (int a = 0; a < 6; a++) yv[a] = slab[(a + 6) * SLABC + col];
}

// In-place: packed-lower SPD matrix -> packed-lower inv(chol(c)).
static __device__ __forceinline__ void chol_inv6(float* c) {
    float L[21];  // off-diagonals hold L[i][j]; diagonal slots hold 1/L[j][j]
#pragma unroll
    for (int j = 0; j < 6; j++) {
        float d = c[P(j, j)];
#pragma unroll
        for (int k = 0; k < j; k++) d = fmaf(-L[P(j, k)], L[P(j, k)], d);
        const float rs = rsqrtf(d);
        L[P(j, j)] = rs;
#pragma unroll
        for (int i = j + 1; i < 6; i++) {
            float s = c[P(i, j)];
#pragma unroll
            for (int k = 0; k < j; k++) s = fmaf(-L[P(i, k)], L[P(j, k)], s);
            L[P(i, j)] = s * rs;
        }
    }
#pragma unroll
    for (int j = 0; j < 6; j++) {
        c[P(j, j)] = L[P(j, j)];
#pragma unroll
        for (int i = j + 1; i < 6; i++) {
            float s = 0.f;
#pragma unroll
            for (int k = j; k < i; k++) s = fmaf(L[P(i, k)], c[P(k, j)], s);
            c[P(i, j)] = -L[P(i, i)] * s;
        }
    }
}

// Epilogue on RAW window sums (CCA is invariant to scaling cov by n).
template <int R>
static __device__ __forceinline__ float cca_epilogue(const Acc& A) {
    constexpr float inv_n = 1.0f / float((2 * R + 1) * (2 * R + 1));
    constexpr float neps = CCA_EPS * float((2 * R + 1) * (2 * R + 1));

    float sxm[6], sym[6];
#pragma unroll
    for (int p = 0; p < 3; p++) {
        up2(A.mx[p], sxm[2 * p], sxm[2 * p + 1]);
        up2(A.my[p], sym[2 * p], sym[2 * p + 1]);
    }
    const u64 cni = bc2(-inv_n);
    u64 nsmx[3], nsmy[3];  // -(S1)/n, packed pairs
#pragma unroll
    for (int p = 0; p < 3; p++) {
        nsmx[p] = mul2v(A.mx[p], cni);
        nsmy[p] = mul2v(A.my[p], cni);
    }
    u64 bx[6], by[6];
#pragma unroll
    for (int a = 0; a < 6; a++) { bx[a] = bc2(sxm[a]); by[a] = bc2(sym[a]); }

    float cxx[21], cyy[21], cxy[36];
    {
        u64 t;
        t = fma2v(A.xx[0], bx[1], nsmx[0]); up2(t, cxx[P(1, 0)], cxx[P(1, 1)]);
        t = fma2v(A.xx[1], bx[2], nsmx[0]); up2(t, cxx[P(2, 0)], cxx[P(2, 1)]);
        t = fma2v(A.xx[2], bx[3], nsmx[0]); up2(t, cxx[P(3, 0)], cxx[P(3, 1)]);
        t = fma2v(A.xx[3], bx[3], nsmx[1]); up2(t, cxx[P(3, 2)], cxx[P(3, 3)]);
        t = fma2v(A.xx[4], bx[4], nsmx[0]); up2(t, cxx[P(4, 0)], cxx[P(4, 1)]);
        t = fma2v(A.xx[5], bx[4], nsmx[1]); up2(t, cxx[P(4, 2)], cxx[P(4, 3)]);
        t = fma2v(A.xx[6], bx[5], nsmx[0]); up2(t, cxx[P(5, 0)], cxx[P(5, 1)]);
        t = fma2v(A.xx[7], bx[5], nsmx[1]); up2(t, cxx[P(5, 2)], cxx[P(5, 3)]);
        t = fma2v(A.xx[8], bx[5], nsmx[2]); up2(t, cxx[P(5, 4)], cxx[P(5, 5)]);
        t = fma2v(A.yy[0], by[1], nsmy[0]); up2(t, cyy[P(1, 0)], cyy[P(1, 1)]);
        t = fma2v(A.yy[1], by[2], nsmy[0]); up2(t, cyy[P(2, 0)], cyy[P(2, 1)]);
        t = fma2v(A.yy[2], by[3], nsmy[0]); up2(t, cyy[P(3, 0)], cyy[P(3, 1)]);
        t = fma2v(A.yy[3], by[3], nsmy[1]); up2(t, cyy[P(3, 2)], cyy[P(3, 3)]);
        t = fma2v(A.yy[4], by[4], nsmy[0]); up2(t, cyy[P(4, 0)], cyy[P(4, 1)]);
        t = fma2v(A.yy[5], by[4], nsmy[1]); up2(t, cyy[P(4, 2)], cyy[P(4, 3)]);
        t = fma2v(A.yy[6], by[5], nsmy[0]); up2(t, cyy[P(5, 0)], cyy[P(5, 1)]);
        t = fma2v(A.yy[7], by[5], nsmy[1]); up2(t, cyy[P(5, 2)], cyy[P(5, 3)]);
        t = fma2v(A.yy[8], by[5], nsmy[2]); up2(t, cyy[P(5, 4)], cyy[P(5, 5)]);
#pragma unroll
        for (int i = 0; i < 6; i++) {
#pragma unroll
            for (int p = 0; p < 3; p++) {
                t = fma2v(A.xy[i * 3 + p], bx[i], nsmy[p]);
                up2(t, cxy[i * 6 + 2 * p], cxy[i * 6 + 2 * p + 1]);
            }
        }
    }
    float nsx0, nsx1, nsx2, nsx3, nsx4, nsx5, nsy0, nsy1, nsy2, nsy3, nsy4, nsy5;
    up2(nsmx[0], nsx0, nsx1); up2(nsmx[1], nsx2, nsx3); up2(nsmx[2], nsx4, nsx5);
    up2(nsmy[0], nsy0, nsy1); up2(nsmy[1], nsy2, nsy3); up2(nsmy[2], nsy4, nsy5);
    cxx[P(0, 0)] = fmaf(sxm[0], nsx0, A.dxx[0]) + neps;
    cxx[P(2, 2)] = fmaf(sxm[2], nsx2, A.dxx[1]) + neps;
    cxx[P(4, 4)] = fmaf(sxm[4], nsx4, A.dxx[2]) + neps;
    cxx[P(1, 1)] += neps; cxx[P(3, 3)] += neps; cxx[P(5, 5)] += neps;
    cyy[P(0, 0)] = fmaf(sym[0], nsy0, A.dyy[0]) + neps;
    cyy[P(2, 2)] = fmaf(sym[2], nsy2, A.dyy[1]) + neps;
    cyy[P(4, 4)] = fmaf(sym[4], nsy4, A.dyy[2]) + neps;
    cyy[P(1, 1)] += neps; cyy[P(3, 3)] += neps; cyy[P(5, 5)] += neps;

    chol_inv6(cxx);  // Mx = inv(chol(n*Cxx)), packed lower
    chol_inv6(cyy);  // My = inv(chol(n*Cyy)), packed lower

    float sim = 0.f;
#pragma unroll
    for (int i = 0; i < 6; i++) {
        float corr = 0.f;
#pragma unroll
        for (int k = i; k < 6; k++) {
            float t = 0.f;
#pragma unroll
            for (int j = 0; j <= i; j++) t = fmaf(cxx[P(i, j)], cxy[j * 6 + k], t);
            corr = fmaf(t, cyy[P(k, i)], corr);
        }
        sim += fabsf(corr);
    }
    return sim * (1.0f / 6.0f);
}

// ---------- tile driver ----------
// Units are row-PAIRS. Prime units p=0..R-1: rows (y0-R+2p, y0-R+2p+1).
// Main units t=0..TR-1: (add row y0+t+R, retire row y0+t-R); step order is
// add -> epilogue/store -> retire, so the prime window is exactly rows
// y0-R .. y0+R-1 (2R rows = R pairs, all uniform pair-units).
template <int R>
static __device__ __forceinline__ void issue_unit(int v, int U, float* __restrict__ sbuf,
                                                  const float* __restrict__ xb,
                                                  const float* __restrict__ yb,
                                                  int x0, int y0, int slot) {
    if (v < U) {
        float* slabA = sbuf + slot * (2 * SLABF);
        int rA, rB;
        if (v < R) { rA = y0 - R + 2 * v; rB = rA + 1; }
        else       { const int t = v - R; rA = y0 + t + R; rB = y0 + t - R; }
        stage_row_async(slabA, xb, yb, refl(rA, HH), x0);
        stage_row_async(slabA + SLABF, xb, yb, refl(rB, HH), x0);
    } else if (threadIdx.x == 0) {
        cp16(sbuf + NPAIR * 2 * SLABF, xb);  // dummy group into scratch
    }
    cp_commit();
}

template <int R>
static __device__ void run_tile(const float* __restrict__ xb,
                                const float* __restrict__ yb,
                                float* __restrict__ ob,
                                int x0, int y0, int ridx, float* __restrict__ sbuf) {
    const int tid = threadIdx.x;
    const int U = R + TR;
    Acc A;
    acc_zero(A);

    // Prologue: depth-2 prefetch (units 0..2, one commit group each).
    issue_unit<R>(0, U, sbuf, xb, yb, x0, y0, 0);
    issue_unit<R>(1, U, sbuf, xb, yb, x0, y0, 1);
    issue_unit<R>(2, U, sbuf, xb, yb, x0, y0, 2);

    int slot = 0;
    int vnext = 3;
    // ---- prime units 0..R-1 ----
#pragma unroll 1
    for (int u = 0; u < R; ++u) {
        cp_wait2();
        __syncthreads();
        const float* slabA = sbuf + slot * (2 * SLABF);
#pragma unroll 1
        for (int dx = 0; dx <= 2 * R; ++dx) {
            const int col = tid + 4 - R + dx;
            float xv[CC], yv[CC];
            load12s(slabA, col, xv, yv);
            sample_fma<1>(xv, yv, A);
            load12s(slabA + SLABF, col, xv, yv);
            sample_fma<1>(xv, yv, A);
        }
        __syncthreads();
        issue_unit<R>(vnext, U, sbuf, xb, yb, x0, y0, slot);
        ++vnext;
        slot = (slot == NPAIR - 1) ? 0 : slot + 1;
    }
    // ---- main units ----
#pragma unroll 1
    for (int t = 0; t < TR; ++t) {
        cp_wait2();
        __syncthreads();
        const float* slabA = sbuf + slot * (2 * SLABF);
        const int yy = y0 + t;
        // add row yy+R
#pragma unroll (R == 2 ? 5 : 3)
        for (int dx = 0; dx <= 2 * R; ++dx) {
            const int col = tid + 4 - R + dx;
            float xv[CC], yv[CC];
            load12s(slabA, col, xv, yv);
            sample_fma<1>(xv, yv, A);
        }
        const float sim = cca_epilogue<R>(A);
        ob[((yy * WW + x0 + tid) << 1) + ridx] = sim;
        // retire row yy-R
#pragma unroll (R == 2 ? 5 : 3)
        for (int dx = 0; dx <= 2 * R; ++dx) {
            const int col = tid + 4 - R + dx;
            float xv[CC], yv[CC];
            load12s(slabA + SLABF, col, xv, yv);
            sample_fma<-1>(xv, yv, A);
        }
        __syncthreads();
        issue_unit<R>(vnext, U, sbuf, xb, yb, x0, y0, slot);
        ++vnext;
        slot = (slot == NPAIR - 1) ? 0 : slot + 1;
    }
}

__global__ void __launch_bounds__(TB, 3)
PatchCCAConv_kernel(const float* __restrict__ x, const float* __restrict__ y,
                    float* __restrict__ out) {
    __shared__ __align__(16) float sbuf[NPAIR * 2 * SLABF + 4];  // 6 slabs + scratch, ~39 KB
    // z = 0,1 -> r=4 (long blocks scheduled first); z = 2,3 -> r=2
    const int b = blockIdx.z & 1;
    const bool is_r4 = blockIdx.z < 2;
    const int x0 = blockIdx.x * TB;
    const int y0 = blockIdx.y * TR;
    const float* xb = x + b * CC * HW;
    const float* yb = y + b * CC * HW;
    float* ob = out + b * (HH * WW * 2);
    if (is_r4)
        run_tile<4>(xb, yb, ob, x0, y0, 1, sbuf);
    else
        run_tile<2>(xb, yb, ob, x0, y0, 0, sbuf);
}

extern "C" void kernel_launch(void* const* d_in, const int* in_sizes, int n_in,
                              void* d_out, int out_size) {
    const float* x = (const float*)d_in[0];
    const float* y = (const float*)d_in[1];
    float* out = (float*)d_out;
    (void)in_sizes; (void)n_in; (void)out_size;

    dim3 block(TB, 1, 1);
    dim3 grid(WW / TB, HH / TR, 4);  // (4, 32, 4): z<2 r=4, z>=2 r=2
    PatchCCAConv_kernel<<<grid, block>>>(x, y, out);
}